// round 1
// baseline (speedup 1.0000x reference)
#include <cuda_runtime.h>
#include <cuda_bf16.h>
#include <cstddef>

#define Bsz 16
#define Lsz 2048
#define Dsz 512
#define Vsz 512
#define NLsz 4
#define Tsz (Bsz * Lsz)  // 32768

// ---------------- scratch (device globals; no allocation allowed) ----------
__device__ float g_y[Tsz * Dsz];        // residual stream          (64 MB)
__device__ float g_z[Tsz * Dsz];        // post-LN / wout out       (64 MB)
__device__ float g_z2[Tsz * Dsz];       // conv out / gated out     (64 MB)
__device__ float g_h[Tsz * Dsz];        // ssm hidden states        (64 MB)
__device__ float g_f[Tsz * 2 * Dsz];    // fc output                (128 MB)
__device__ float g_gate[Tsz];           // scalar gates
__device__ float g_w3[3 * Dsz * Dsz];   // repacked conv weights [h][o][i]

// ---------------- embed: one-hot ------------------------------------------
__global__ void embed_k(const int* __restrict__ x, float* __restrict__ y) {
    int idx = blockIdx.x * blockDim.x + threadIdx.x;  // over T*D
    int t = idx >> 9;
    int d = idx & 511;
    y[idx] = (x[t] == d) ? 1.0f : 0.0f;
}

// ---------------- layernorm: one block (128 thr) per token ----------------
__global__ void ln_k(const float* __restrict__ in, float* __restrict__ out,
                     const float* __restrict__ gamma, const float* __restrict__ beta) {
    int t = blockIdx.x;
    int tid = threadIdx.x;  // 0..127, 4 floats each
    const float4* rp = (const float4*)(in + (size_t)t * Dsz);
    float4 v = rp[tid];
    float s = v.x + v.y + v.z + v.w;
#pragma unroll
    for (int o = 16; o; o >>= 1) s += __shfl_xor_sync(0xffffffffu, s, o);
    __shared__ float sm[4];
    if ((tid & 31) == 0) sm[tid >> 5] = s;
    __syncthreads();
    float mean = (sm[0] + sm[1] + sm[2] + sm[3]) * (1.0f / Dsz);
    float dx = v.x - mean, dy = v.y - mean, dz = v.z - mean, dw = v.w - mean;
    float q = dx * dx + dy * dy + dz * dz + dw * dw;
#pragma unroll
    for (int o = 16; o; o >>= 1) q += __shfl_xor_sync(0xffffffffu, q, o);
    __syncthreads();
    if ((tid & 31) == 0) sm[tid >> 5] = q;
    __syncthreads();
    float var = (sm[0] + sm[1] + sm[2] + sm[3]) * (1.0f / Dsz);
    float rstd = rsqrtf(var + 1e-5f);
    float4 g4 = ((const float4*)gamma)[tid];
    float4 b4 = ((const float4*)beta)[tid];
    float4 o4;
    o4.x = dx * rstd * g4.x + b4.x;
    o4.y = dy * rstd * g4.y + b4.y;
    o4.z = dz * rstd * g4.z + b4.z;
    o4.w = dw * rstd * g4.w + b4.w;
    ((float4*)(out + (size_t)t * Dsz))[tid] = o4;
}

// ---------------- conv weight repack: w3[h][o][i] = cw[o][i][h] ------------
__global__ void repack_k(const float* __restrict__ cw, float* __restrict__ w3) {
    int idx = blockIdx.x * blockDim.x + threadIdx.x;  // over 3*D*D
    int h = idx / (Dsz * Dsz);
    int r = idx - h * (Dsz * Dsz);
    int o = r >> 9;
    int i = r & 511;
    w3[idx] = cw[((size_t)o * Dsz + i) * 3 + h];
}

// ---------------- SGEMM: C[m,n] (+)= sum_k A[m+shift,k] * W[n,k] (+ bias) --
// M = Tsz fixed, K = 512 fixed. N in {512, 1024}. shift in {-1,0,1} applies
// within each length-L sequence (zero pad outside). flags: 1=addBias 2=accum.
__global__ __launch_bounds__(256, 2) void sgemm_k(
    const float* __restrict__ A, const float* __restrict__ W,
    const float* __restrict__ bias, float* __restrict__ C,
    int N, int shift, int flags) {
    __shared__ float As[8][128];
    __shared__ float Ws[8][128];
    int tid = threadIdx.x;
    int ty = tid >> 4, tx = tid & 15;
    int mBase = blockIdx.y << 7;
    int nBase = blockIdx.x << 7;

    int aRow = tid >> 1;          // 0..127
    int k4 = (tid & 1) << 2;      // 0 or 4

    int row = mBase + aRow;
    int l = row & (Lsz - 1);
    int ls = l + shift;
    bool valid = ((unsigned)ls < (unsigned)Lsz);
    const float* aptr = A + (size_t)(valid ? (row + shift) : row) * 512 + k4;
    const float* wptr = W + (size_t)(nBase + aRow) * 512 + k4;

    float4 av = valid ? *(const float4*)aptr : make_float4(0.f, 0.f, 0.f, 0.f);
    float4 wv = *(const float4*)wptr;

    float acc[8][8];
#pragma unroll
    for (int i = 0; i < 8; i++)
#pragma unroll
        for (int j = 0; j < 8; j++) acc[i][j] = 0.f;

    for (int kt = 0; kt < 512; kt += 8) {
        As[k4 + 0][aRow] = av.x; As[k4 + 1][aRow] = av.y;
        As[k4 + 2][aRow] = av.z; As[k4 + 3][aRow] = av.w;
        Ws[k4 + 0][aRow] = wv.x; Ws[k4 + 1][aRow] = wv.y;
        Ws[k4 + 2][aRow] = wv.z; Ws[k4 + 3][aRow] = wv.w;
        __syncthreads();
        if (kt + 8 < 512) {  // register prefetch of next tile
            av = valid ? *(const float4*)(aptr + kt + 8) : make_float4(0.f, 0.f, 0.f, 0.f);
            wv = *(const float4*)(wptr + kt + 8);
        }
#pragma unroll
        for (int k = 0; k < 8; k++) {
            float4 a0 = *(const float4*)&As[k][ty << 2];
            float4 a1 = *(const float4*)&As[k][64 + (ty << 2)];
            float4 w0 = *(const float4*)&Ws[k][tx << 2];
            float4 w1 = *(const float4*)&Ws[k][64 + (tx << 2)];
            float am[8] = {a0.x, a0.y, a0.z, a0.w, a1.x, a1.y, a1.z, a1.w};
            float wn[8] = {w0.x, w0.y, w0.z, w0.w, w1.x, w1.y, w1.z, w1.w};
#pragma unroll
            for (int i = 0; i < 8; i++)
#pragma unroll
                for (int j = 0; j < 8; j++)
                    acc[i][j] = fmaf(am[i], wn[j], acc[i][j]);
        }
        __syncthreads();
    }

    bool addB = (flags & 1) != 0;
    bool accum = (flags & 2) != 0;
#pragma unroll
    for (int ih = 0; ih < 2; ih++)
#pragma unroll
        for (int i = 0; i < 4; i++) {
            int r = mBase + ih * 64 + (ty << 2) + i;
            float* crow = C + (size_t)r * N + nBase;
#pragma unroll
            for (int jh = 0; jh < 2; jh++) {
                int col = jh * 64 + (tx << 2);
                float4 v4;
                v4.x = acc[ih * 4 + i][jh * 4 + 0];
                v4.y = acc[ih * 4 + i][jh * 4 + 1];
                v4.z = acc[ih * 4 + i][jh * 4 + 2];
                v4.w = acc[ih * 4 + i][jh * 4 + 3];
                if (addB) {
                    float4 bb = *(const float4*)(bias + nBase + col);
                    v4.x += bb.x; v4.y += bb.y; v4.z += bb.z; v4.w += bb.w;
                }
                if (accum) {
                    float4 o = *(const float4*)(crow + col);
                    v4.x += o.x; v4.y += o.y; v4.z += o.z; v4.w += o.w;
                }
                *(float4*)(crow + col) = v4;
            }
        }
}

// ---------------- scalar gate: g[t] = sigmoid(dot(z[t,:], wg) + bg) --------
__global__ void gate_k(const float* __restrict__ z, const float* __restrict__ wg,
                       const float* __restrict__ bg, float* __restrict__ gout) {
    int warp = (blockIdx.x * blockDim.x + threadIdx.x) >> 5;
    int lane = threadIdx.x & 31;
    const float4* row = (const float4*)(z + (size_t)warp * Dsz);
    const float4* w = (const float4*)wg;
    float s = 0.f;
#pragma unroll
    for (int i = 0; i < 4; i++) {
        float4 a = row[lane + 32 * i];
        float4 b = w[lane + 32 * i];
        s += a.x * b.x + a.y * b.y + a.z * b.z + a.w * b.w;
    }
#pragma unroll
    for (int o = 16; o; o >>= 1) s += __shfl_xor_sync(0xffffffffu, s, o);
    if (lane == 0) gout[warp] = 1.0f / (1.0f + expf(-(s + bg[0])));
}

// ---------------- sequential scan: h_l = h + g_l*(x_l - h) -----------------
__global__ void scan_k(const float* __restrict__ x, const float* __restrict__ g,
                       float* __restrict__ h) {
    int b = blockIdx.x >> 2;                       // 16 batches
    int d = ((blockIdx.x & 3) << 7) + threadIdx.x; // 4 chunks * 128
    size_t base = (size_t)b * Lsz * Dsz + d;
    const float* gb = g + (size_t)b * Lsz;
    float hv = 0.f;
    for (int l = 0; l < Lsz; l += 8) {
        float xs[8], gs[8];
#pragma unroll
        for (int j = 0; j < 8; j++) {
            xs[j] = x[base + (size_t)(l + j) * Dsz];
            gs[j] = gb[l + j];
        }
#pragma unroll
        for (int j = 0; j < 8; j++) {
            hv = fmaf(gs[j], xs[j] - hv, hv);
            h[base + (size_t)(l + j) * Dsz] = hv;
        }
    }
}

// ---------------- gated MLP elementwise: sigmoid(gate)*val -----------------
__global__ void gated_k(const float* __restrict__ f, float* __restrict__ out) {
    int idx = blockIdx.x * blockDim.x + threadIdx.x;  // over T*D
    int t = idx >> 9;
    int e = idx & 511;
    float gt = f[(size_t)t * 1024 + e];
    float vl = f[(size_t)t * 1024 + 512 + e];
    out[idx] = vl / (1.0f + expf(-gt));
}

// ---------------- launch ---------------------------------------------------
extern "C" void kernel_launch(void* const* d_in, const int* in_sizes, int n_in,
                              void* d_out, int out_size) {
    const int* x = (const int*)d_in[0];
    const float* ln_g = (const float*)d_in[1];
    const float* ln_b = (const float*)d_in[2];
    const float* conv_w = (const float*)d_in[3];
    const float* conv_b = (const float*)d_in[4];
    const float* wg = (const float*)d_in[5];
    const float* bg = (const float*)d_in[6];
    const float* wout = (const float*)d_in[7];
    const float* bout = (const float*)d_in[8];
    const float* fc_w = (const float*)d_in[9];
    const float* fc_b = (const float*)d_in[10];
    const float* mo_w = (const float*)d_in[11];
    const float* mo_b = (const float*)d_in[12];
    const float* lnf_g = (const float*)d_in[13];
    const float* lnf_b = (const float*)d_in[14];
    const float* head_w = (const float*)d_in[15];
    const float* head_b = (const float*)d_in[16];

    float *y, *z, *z2, *h, *f, *gt, *w3;
    cudaGetSymbolAddress((void**)&y, g_y);
    cudaGetSymbolAddress((void**)&z, g_z);
    cudaGetSymbolAddress((void**)&z2, g_z2);
    cudaGetSymbolAddress((void**)&h, g_h);
    cudaGetSymbolAddress((void**)&f, g_f);
    cudaGetSymbolAddress((void**)&gt, g_gate);
    cudaGetSymbolAddress((void**)&w3, g_w3);

    const dim3 gemm_n512(Dsz / 128, Tsz / 128);      // (4, 256)
    const dim3 gemm_n1024(2 * Dsz / 128, Tsz / 128); // (8, 256)

    embed_k<<<(Tsz * Dsz) / 256, 256>>>(x, y);

    for (int i = 0; i < NLsz; i++) {
        const float* lg = ln_g + (size_t)i * Dsz;
        const float* lb = ln_b + (size_t)i * Dsz;
        const float* cw = conv_w + (size_t)i * Dsz * Dsz * 3;
        const float* cb = conv_b + (size_t)i * Dsz;
        const float* wgi = wg + (size_t)i * Dsz;
        const float* bgi = bg + i;
        const float* woi = wout + (size_t)i * Dsz * Dsz;
        const float* boi = bout + (size_t)i * Dsz;
        const float* fwi = fc_w + (size_t)i * 2 * Dsz * Dsz;
        const float* fbi = fc_b + (size_t)i * 2 * Dsz;
        const float* mwi = mo_w + (size_t)i * Dsz * Dsz;
        const float* mbi = mo_b + (size_t)i * Dsz;

        ln_k<<<Tsz, 128>>>(y, z, lg, lb);
        repack_k<<<(3 * Dsz * Dsz) / 256, 256>>>(cw, w3);
        // conv as 3 shift-masked GEMM passes: out[l] += W_h^T in[l + h - 1]
        sgemm_k<<<gemm_n512, 256>>>(z, w3, cb, z2, Dsz, -1, 1);
        sgemm_k<<<gemm_n512, 256>>>(z, w3 + Dsz * Dsz, nullptr, z2, Dsz, 0, 2);
        sgemm_k<<<gemm_n512, 256>>>(z, w3 + 2 * Dsz * Dsz, nullptr, z2, Dsz, 1, 2);
        gate_k<<<Tsz / 4, 128>>>(z2, wgi, bgi, gt);
        scan_k<<<64, 128>>>(z2, gt, h);
        sgemm_k<<<gemm_n512, 256>>>(h, woi, boi, z, Dsz, 0, 1);
        sgemm_k<<<gemm_n1024, 256>>>(z, fwi, fbi, f, 2 * Dsz, 0, 1);
        gated_k<<<(Tsz * Dsz) / 256, 256>>>(f, z2);
        // mo GEMM with residual add fused (accumulate into y)
        sgemm_k<<<gemm_n512, 256>>>(z2, mwi, mbi, y, Dsz, 0, 3);
    }

    ln_k<<<Tsz, 128>>>(y, z, lnf_g, lnf_b);
    sgemm_k<<<gemm_n512, 256>>>(z, head_w, head_b, (float*)d_out, Dsz, 0, 1);
}

// round 3
// speedup vs baseline: 2.3238x; 2.3238x over previous
#include <cuda_runtime.h>
#include <cuda_bf16.h>
#include <cstdint>
#include <cstddef>

#define Bsz 16
#define Lsz 2048
#define Dsz 512
#define NLsz 4
#define Tsz (Bsz * Lsz)  // 32768

// ---------------- scratch (device globals; no allocation allowed) ----------
__device__ float g_y[Tsz * Dsz];          // residual (fp32)
__device__ float g_z2[Tsz * Dsz];         // conv out (fp32)
__device__ float g_f[Tsz * 2 * Dsz];      // fc out (fp32)
__device__ float g_gate[Tsz];
__device__ __nv_bfloat16 g_zh[Tsz * Dsz], g_zl[Tsz * Dsz];   // LN / wout out
__device__ __nv_bfloat16 g_hh[Tsz * Dsz], g_hl[Tsz * Dsz];   // scan out
__device__ __nv_bfloat16 g_gh[Tsz * Dsz], g_gl[Tsz * Dsz];   // gated out
__device__ __nv_bfloat16 g_wah[3 * Dsz * Dsz], g_wal[3 * Dsz * Dsz];  // weights

// ---------------- helpers ---------------------------------------------------
__device__ __forceinline__ uint32_t smem_u32(const void* p) {
    return (uint32_t)__cvta_generic_to_shared(p);
}
__device__ __forceinline__ uint32_t swz(uint32_t x) { return x ^ ((x >> 3) & 0x70); }

__device__ __forceinline__ void cp16(uint32_t dst, const void* src, bool v) {
    int sz = v ? 16 : 0;
    asm volatile("cp.async.cg.shared.global [%0], [%1], 16, %2;"
                 :: "r"(dst), "l"(src), "r"(sz) : "memory");
}
#define CP_COMMIT() asm volatile("cp.async.commit_group;" ::: "memory")

#define LDSM_X4(r, a)                                                          \
    asm volatile("ldmatrix.sync.aligned.m8n8.x4.shared.b16 {%0,%1,%2,%3}, [%4];" \
                 : "=r"((r)[0]), "=r"((r)[1]), "=r"((r)[2]), "=r"((r)[3]) : "r"(a))

#define MMA_BF16(d, a, b0, b1)                                                 \
    asm volatile(                                                              \
        "mma.sync.aligned.m16n8k16.row.col.f32.bf16.bf16.f32 "                 \
        "{%0,%1,%2,%3},{%4,%5,%6,%7},{%8,%9},{%0,%1,%2,%3};"                   \
        : "+f"((d)[0]), "+f"((d)[1]), "+f"((d)[2]), "+f"((d)[3])               \
        : "r"((a)[0]), "r"((a)[1]), "r"((a)[2]), "r"((a)[3]), "r"(b0), "r"(b1))

__device__ __forceinline__ void split2(float a, float b, __nv_bfloat162& hi,
                                       __nv_bfloat162& lo) {
    hi = __floats2bfloat162_rn(a, b);
    lo = __floats2bfloat162_rn(a - __bfloat162float(hi.x), b - __bfloat162float(hi.y));
}

// ============================================================================
// bf16-split GEMM via mma.sync: C[m,n] (+)= sum_p sum_k A[m+sh_p,k] * Wp[n,k]
// A = (Ah,Al) bf16 [32768, 512]; W = (Wh,Wl) bf16 [N, 512] per pass (stride D*D).
// flags: 1=addBias, 2=accumulate (fp32 out), 4=split bf16 output (Ch/Cl).
// ============================================================================
#define STAGE_B 65536
#define GSMEM (2 * STAGE_B)

__global__ __launch_bounds__(256, 1)
void mma_gemm_k(const __nv_bfloat16* __restrict__ Ah, const __nv_bfloat16* __restrict__ Al,
                const __nv_bfloat16* __restrict__ Wh, const __nv_bfloat16* __restrict__ Wl,
                const float* __restrict__ bias, float* __restrict__ Cf,
                __nv_bfloat16* __restrict__ Ch, __nv_bfloat16* __restrict__ Cl,
                int N, int nPasses, int s0, int s1, int s2, int flags) {
    extern __shared__ char smem[];
    const uint32_t smb = smem_u32(smem);
    const int tid = threadIdx.x, lane = tid & 31, wid = tid >> 5;
    const int mBase = blockIdx.y << 7, nBase = blockIdx.x << 7;
    const int wm = wid & 3, wn = wid >> 2;

    float acc[2][8][4];
#pragma unroll
    for (int t = 0; t < 2; t++)
#pragma unroll
        for (int j = 0; j < 8; j++)
#pragma unroll
            for (int q = 0; q < 4; q++) acc[t][j][q] = 0.f;

    const int total = nPasses * 8;
    const int rBase = tid >> 3, col16 = tid & 7;

    // ---- stage issuer ----
    auto issue = [&](int idx) {
        const int p = idx >> 3, c8 = idx & 7;
        const int shift = (p == 0) ? s0 : ((p == 1) ? s1 : s2);
        const size_t wOff = (size_t)p * (Dsz * Dsz);
        const uint32_t sb = smb + (uint32_t)(idx & 1) * STAGE_B;
        const int kOff = c8 * 64 + col16 * 8;
#pragma unroll
        for (int c = 0; c < 4; c++) {
            const int row = rBase + c * 32;
            const uint32_t dsw = swz((uint32_t)(row * 128 + col16 * 16));
            // A rows (shifted within sequence, zero-fill outside)
            const int m = mBase + row;
            const int l = m & (Lsz - 1);
            const bool valid = ((unsigned)(l + shift) < (unsigned)Lsz);
            const size_t aoff = (size_t)(m + (valid ? shift : 0)) * Dsz + kOff;
            cp16(sb + dsw, Ah + aoff, valid);
            cp16(sb + 16384 + dsw, Al + aoff, valid);
            // W rows
            const size_t woff = wOff + (size_t)(nBase + row) * Dsz + kOff;
            cp16(sb + 32768 + dsw, Wh + woff, true);
            cp16(sb + 49152 + dsw, Wl + woff, true);
        }
        CP_COMMIT();
    };

    issue(0);
    for (int idx = 0; idx < total; idx++) {
        if (idx + 1 < total) {
            issue(idx + 1);
            asm volatile("cp.async.wait_group 1;" ::: "memory");
        } else {
            asm volatile("cp.async.wait_group 0;" ::: "memory");
        }
        __syncthreads();
        // ---- compute on stage idx&1 ----
        const uint32_t sb = smb + (uint32_t)(idx & 1) * STAGE_B;
#pragma unroll
        for (int kk = 0; kk < 4; kk++) {
            uint32_t ah[2][4], al[2][4];
#pragma unroll
            for (int t = 0; t < 2; t++) {
                const int row = wm * 32 + t * 16 + (lane & 15);
                const uint32_t off =
                    swz((uint32_t)(row * 128 + kk * 32 + (lane >> 4) * 16));
                LDSM_X4(ah[t], sb + off);
                LDSM_X4(al[t], sb + 16384 + off);
            }
#pragma unroll
            for (int jp = 0; jp < 4; jp++) {
                const int nrow = wn * 64 + jp * 16 + (lane & 7) + ((lane >> 4) << 3);
                const uint32_t off =
                    swz((uint32_t)(nrow * 128 + kk * 32 + ((lane >> 3) & 1) * 16));
                uint32_t bh[4], bl[4];
                LDSM_X4(bh, sb + 32768 + off);
                LDSM_X4(bl, sb + 49152 + off);
#pragma unroll
                for (int t = 0; t < 2; t++) {
#pragma unroll
                    for (int jj = 0; jj < 2; jj++) {
                        float* d = acc[t][jp * 2 + jj];
                        MMA_BF16(d, ah[t], bh[jj * 2], bh[jj * 2 + 1]);
                        MMA_BF16(d, ah[t], bl[jj * 2], bl[jj * 2 + 1]);
                        MMA_BF16(d, al[t], bh[jj * 2], bh[jj * 2 + 1]);
                    }
                }
            }
        }
        __syncthreads();
    }

    // ---- epilogue ----
    const bool addB = (flags & 1) != 0;
    const bool accum = (flags & 2) != 0;
    const bool splitO = (flags & 4) != 0;
#pragma unroll
    for (int t = 0; t < 2; t++) {
#pragma unroll
        for (int j = 0; j < 8; j++) {
            const int r0 = mBase + wm * 32 + t * 16 + (lane >> 2);
            const int col = nBase + wn * 64 + j * 8 + (lane & 3) * 2;
            float b0 = 0.f, b1 = 0.f;
            if (addB) { b0 = bias[col]; b1 = bias[col + 1]; }
            float v0 = acc[t][j][0] + b0, v1 = acc[t][j][1] + b1;
            float v2 = acc[t][j][2] + b0, v3 = acc[t][j][3] + b1;
            const size_t o0 = (size_t)r0 * N + col;
            const size_t o1 = (size_t)(r0 + 8) * N + col;
            if (splitO) {
                __nv_bfloat162 h, lo;
                split2(v0, v1, h, lo);
                *(__nv_bfloat162*)(Ch + o0) = h;
                *(__nv_bfloat162*)(Cl + o0) = lo;
                split2(v2, v3, h, lo);
                *(__nv_bfloat162*)(Ch + o1) = h;
                *(__nv_bfloat162*)(Cl + o1) = lo;
            } else {
                if (accum) {
                    float2 p0 = *(float2*)(Cf + o0);
                    float2 p1 = *(float2*)(Cf + o1);
                    v0 += p0.x; v1 += p0.y; v2 += p1.x; v3 += p1.y;
                }
                *(float2*)(Cf + o0) = make_float2(v0, v1);
                *(float2*)(Cf + o1) = make_float2(v2, v3);
            }
        }
    }
}

// ---------------- embed: one-hot (fp32 residual) ---------------------------
__global__ void embed_k(const int* __restrict__ x, float* __restrict__ y) {
    int idx = blockIdx.x * blockDim.x + threadIdx.x;
    int t = idx >> 9, d = idx & 511;
    y[idx] = (x[t] == d) ? 1.0f : 0.0f;
}

// ---------------- layernorm with fused bf16 hi/lo split ---------------------
__global__ void ln_split_k(const float* __restrict__ in,
                           __nv_bfloat16* __restrict__ oh, __nv_bfloat16* __restrict__ ol,
                           const float* __restrict__ gamma, const float* __restrict__ beta) {
    int t = blockIdx.x, tid = threadIdx.x;  // 128 thr, 4 floats each
    const float4* rp = (const float4*)(in + (size_t)t * Dsz);
    float4 v = rp[tid];
    float s = v.x + v.y + v.z + v.w;
#pragma unroll
    for (int o = 16; o; o >>= 1) s += __shfl_xor_sync(0xffffffffu, s, o);
    __shared__ float smr[4];
    if ((tid & 31) == 0) smr[tid >> 5] = s;
    __syncthreads();
    float mean = (smr[0] + smr[1] + smr[2] + smr[3]) * (1.0f / Dsz);
    float dx = v.x - mean, dy = v.y - mean, dz = v.z - mean, dw = v.w - mean;
    float q = dx * dx + dy * dy + dz * dz + dw * dw;
#pragma unroll
    for (int o = 16; o; o >>= 1) q += __shfl_xor_sync(0xffffffffu, q, o);
    __syncthreads();
    if ((tid & 31) == 0) smr[tid >> 5] = q;
    __syncthreads();
    float var = (smr[0] + smr[1] + smr[2] + smr[3]) * (1.0f / Dsz);
    float rstd = rsqrtf(var + 1e-5f);
    float4 g4 = ((const float4*)gamma)[tid];
    float4 b4 = ((const float4*)beta)[tid];
    float f0 = dx * rstd * g4.x + b4.x, f1 = dy * rstd * g4.y + b4.y;
    float f2 = dz * rstd * g4.z + b4.z, f3 = dw * rstd * g4.w + b4.w;
    __nv_bfloat162 h01, l01, h23, l23;
    split2(f0, f1, h01, l01);
    split2(f2, f3, h23, l23);
    __nv_bfloat162* ph = (__nv_bfloat162*)(oh + (size_t)t * Dsz);
    __nv_bfloat162* pl = (__nv_bfloat162*)(ol + (size_t)t * Dsz);
    ph[2 * tid] = h01; ph[2 * tid + 1] = h23;
    pl[2 * tid] = l01; pl[2 * tid + 1] = l23;
}

// ---------------- conv weight repack + split: [h][o][i] <- cw[o][i][h] ------
__global__ void cwsplit_k(const float* __restrict__ cw,
                          __nv_bfloat16* __restrict__ wh, __nv_bfloat16* __restrict__ wl) {
    int idx = blockIdx.x * blockDim.x + threadIdx.x;  // over 3*D*D
    int h = idx / (Dsz * Dsz);
    int r = idx - h * (Dsz * Dsz);
    int o = r >> 9, i = r & 511;
    float v = cw[((size_t)o * Dsz + i) * 3 + h];
    __nv_bfloat16 hi = __float2bfloat16(v);
    wh[idx] = hi;
    wl[idx] = __float2bfloat16(v - __bfloat162float(hi));
}

// ---------------- generic weight split --------------------------------------
__global__ void wsplit_k(const float* __restrict__ w, __nv_bfloat16* __restrict__ wh,
                         __nv_bfloat16* __restrict__ wl, int n) {
    int idx = blockIdx.x * blockDim.x + threadIdx.x;
    if (idx >= n) return;
    float v = w[idx];
    __nv_bfloat16 hi = __float2bfloat16(v);
    wh[idx] = hi;
    wl[idx] = __float2bfloat16(v - __bfloat162float(hi));
}

// ---------------- scalar gate ------------------------------------------------
__global__ void gate_k(const float* __restrict__ z, const float* __restrict__ wg,
                       const float* __restrict__ bg, float* __restrict__ gout) {
    int warp = (blockIdx.x * blockDim.x + threadIdx.x) >> 5;
    int lane = threadIdx.x & 31;
    const float4* row = (const float4*)(z + (size_t)warp * Dsz);
    const float4* w = (const float4*)wg;
    float s = 0.f;
#pragma unroll
    for (int i = 0; i < 4; i++) {
        float4 a = row[lane + 32 * i];
        float4 b = w[lane + 32 * i];
        s += a.x * b.x + a.y * b.y + a.z * b.z + a.w * b.w;
    }
#pragma unroll
    for (int o = 16; o; o >>= 1) s += __shfl_xor_sync(0xffffffffu, s, o);
    if (lane == 0) gout[warp] = 1.0f / (1.0f + expf(-(s + bg[0])));
}

// ---------------- sequential scan, split output ------------------------------
__global__ void scan_split_k(const float* __restrict__ x, const float* __restrict__ g,
                             __nv_bfloat16* __restrict__ hh, __nv_bfloat16* __restrict__ hl) {
    int b = blockIdx.x >> 2;
    int d = ((blockIdx.x & 3) << 7) + threadIdx.x;
    size_t base = (size_t)b * Lsz * Dsz + d;
    const float* gb = g + (size_t)b * Lsz;
    float hv = 0.f;
    for (int l = 0; l < Lsz; l += 8) {
        float xs[8], gs[8];
#pragma unroll
        for (int j = 0; j < 8; j++) {
            xs[j] = x[base + (size_t)(l + j) * Dsz];
            gs[j] = gb[l + j];
        }
#pragma unroll
        for (int j = 0; j < 8; j++) {
            hv = fmaf(gs[j], xs[j] - hv, hv);
            __nv_bfloat16 hi = __float2bfloat16(hv);
            size_t o = base + (size_t)(l + j) * Dsz;
            hh[o] = hi;
            hl[o] = __float2bfloat16(hv - __bfloat162float(hi));
        }
    }
}

// ---------------- gated MLP elementwise, split output ------------------------
__global__ void gated_split_k(const float* __restrict__ f,
                              __nv_bfloat16* __restrict__ oh, __nv_bfloat16* __restrict__ ol) {
    int idx = blockIdx.x * blockDim.x + threadIdx.x;  // over T*D
    int t = idx >> 9, e = idx & 511;
    float gt = f[(size_t)t * 1024 + e];
    float vl = f[(size_t)t * 1024 + 512 + e];
    float v = vl / (1.0f + expf(-gt));
    __nv_bfloat16 hi = __float2bfloat16(v);
    oh[idx] = hi;
    ol[idx] = __float2bfloat16(v - __bfloat162float(hi));
}

// ---------------- launch ------------------------------------------------------
extern "C" void kernel_launch(void* const* d_in, const int* in_sizes, int n_in,
                              void* d_out, int out_size) {
    const int* x = (const int*)d_in[0];
    const float* ln_g = (const float*)d_in[1];
    const float* ln_b = (const float*)d_in[2];
    const float* conv_w = (const float*)d_in[3];
    const float* conv_b = (const float*)d_in[4];
    const float* wg = (const float*)d_in[5];
    const float* bg = (const float*)d_in[6];
    const float* wout = (const float*)d_in[7];
    const float* bout = (const float*)d_in[8];
    const float* fc_w = (const float*)d_in[9];
    const float* fc_b = (const float*)d_in[10];
    const float* mo_w = (const float*)d_in[11];
    const float* mo_b = (const float*)d_in[12];
    const float* lnf_g = (const float*)d_in[13];
    const float* lnf_b = (const float*)d_in[14];
    const float* head_w = (const float*)d_in[15];
    const float* head_b = (const float*)d_in[16];

    float *y, *z2, *f, *gt;
    __nv_bfloat16 *zh, *zl, *hh, *hl, *gh, *gl, *wah, *wal;
    cudaGetSymbolAddress((void**)&y, g_y);
    cudaGetSymbolAddress((void**)&z2, g_z2);
    cudaGetSymbolAddress((void**)&f, g_f);
    cudaGetSymbolAddress((void**)&gt, g_gate);
    cudaGetSymbolAddress((void**)&zh, g_zh);
    cudaGetSymbolAddress((void**)&zl, g_zl);
    cudaGetSymbolAddress((void**)&hh, g_hh);
    cudaGetSymbolAddress((void**)&hl, g_hl);
    cudaGetSymbolAddress((void**)&gh, g_gh);
    cudaGetSymbolAddress((void**)&gl, g_gl);
    cudaGetSymbolAddress((void**)&wah, g_wah);
    cudaGetSymbolAddress((void**)&wal, g_wal);

    cudaFuncSetAttribute(mma_gemm_k, cudaFuncAttributeMaxDynamicSharedMemorySize, GSMEM);

    const dim3 g512(4, Tsz / 128);
    const dim3 g1024(8, Tsz / 128);
    const int DD = Dsz * Dsz;

    embed_k<<<(Tsz * Dsz) / 256, 256>>>(x, y);

    for (int i = 0; i < NLsz; i++) {
        const float* lg = ln_g + (size_t)i * Dsz;
        const float* lb = ln_b + (size_t)i * Dsz;
        const float* cw = conv_w + (size_t)i * DD * 3;
        const float* cb = conv_b + (size_t)i * Dsz;
        const float* wgi = wg + (size_t)i * Dsz;
        const float* bgi = bg + i;
        const float* woi = wout + (size_t)i * DD;
        const float* boi = bout + (size_t)i * Dsz;
        const float* fwi = fc_w + (size_t)i * 2 * DD;
        const float* fbi = fc_b + (size_t)i * 2 * Dsz;
        const float* mwi = mo_w + (size_t)i * DD;
        const float* mbi = mo_b + (size_t)i * Dsz;

        ln_split_k<<<Tsz, 128>>>(y, zh, zl, lg, lb);
        cwsplit_k<<<(3 * DD) / 256, 256>>>(cw, wah, wal);
        // conv: 3 shifted passes accumulated in registers, bias in epilogue
        mma_gemm_k<<<g512, 256, GSMEM>>>(zh, zl, wah, wal, cb, z2, nullptr, nullptr,
                                         Dsz, 3, -1, 0, 1, 1);
        gate_k<<<Tsz / 4, 128>>>(z2, wgi, bgi, gt);
        scan_split_k<<<64, 128>>>(z2, gt, hh, hl);
        wsplit_k<<<DD / 256, 256>>>(woi, wah, wal, DD);
        // wout GEMM: split-bf16 output straight into zh/zl for the fc GEMM
        mma_gemm_k<<<g512, 256, GSMEM>>>(hh, hl, wah, wal, boi, nullptr, zh, zl,
                                         Dsz, 1, 0, 0, 0, 5);
        wsplit_k<<<(2 * DD) / 256, 256>>>(fwi, wah, wal, 2 * DD);
        mma_gemm_k<<<g1024, 256, GSMEM>>>(zh, zl, wah, wal, fbi, f, nullptr, nullptr,
                                          2 * Dsz, 1, 0, 0, 0, 1);
        gated_split_k<<<(Tsz * Dsz) / 256, 256>>>(f, gh, gl);
        wsplit_k<<<DD / 256, 256>>>(mwi, wah, wal, DD);
        // mo GEMM with residual accumulate into y (fp32)
        mma_gemm_k<<<g512, 256, GSMEM>>>(gh, gl, wah, wal, mbi, y, nullptr, nullptr,
                                         Dsz, 1, 0, 0, 0, 3);
    }

    ln_split_k<<<Tsz, 128>>>(y, zh, zl, lnf_g, lnf_b);
    wsplit_k<<<DD / 256, 256>>>(head_w, wah, wal, DD);
    mma_gemm_k<<<g512, 256, GSMEM>>>(zh, zl, wah, wal, head_b, (float*)d_out,
                                     nullptr, nullptr, Dsz, 1, 0, 0, 0, 1);
}

// round 4
// speedup vs baseline: 2.4817x; 1.0679x over previous
#include <cuda_runtime.h>
#include <cuda_bf16.h>
#include <cstdint>
#include <cstddef>

#define Bsz 16
#define Lsz 2048
#define Dsz 512
#define NLsz 4
#define Tsz (Bsz * Lsz)  // 32768
#define DD (Dsz * Dsz)

// weight arena offsets (units of DD)
#define W_CONV(i) ((size_t)(i) * 3 * DD)
#define W_WOUT(i) ((size_t)(12 + (i)) * DD)
#define W_FC(i)   ((size_t)(16 + 2 * (i)) * DD)
#define W_MO(i)   ((size_t)(24 + (i)) * DD)
#define W_HEAD    ((size_t)28 * DD)

// ---------------- scratch (device globals; no allocation allowed) ----------
__device__ float g_y[Tsz * Dsz];          // residual (fp32)
__device__ float g_z2[Tsz * Dsz];         // conv out (fp32)
__device__ float g_gate[Tsz];
__device__ __nv_bfloat16 g_zh[Tsz * Dsz], g_zl[Tsz * Dsz];   // LN / wout out
__device__ __nv_bfloat16 g_hh[Tsz * Dsz], g_hl[Tsz * Dsz];   // scan out
__device__ __nv_bfloat16 g_gh[Tsz * Dsz], g_gl[Tsz * Dsz];   // gated out
__device__ __nv_bfloat16 g_wh[29 * DD], g_wl[29 * DD];       // all weights hi/lo

// ---------------- helpers ---------------------------------------------------
__device__ __forceinline__ uint32_t smem_u32(const void* p) {
    return (uint32_t)__cvta_generic_to_shared(p);
}
__device__ __forceinline__ uint32_t swz(uint32_t x) { return x ^ ((x >> 3) & 0x70); }

__device__ __forceinline__ void cp16(uint32_t dst, const void* src, bool v) {
    int sz = v ? 16 : 0;
    asm volatile("cp.async.cg.shared.global [%0], [%1], 16, %2;"
                 :: "r"(dst), "l"(src), "r"(sz) : "memory");
}
#define CP_COMMIT() asm volatile("cp.async.commit_group;" ::: "memory")

#define LDSM_X4(r, a)                                                          \
    asm volatile("ldmatrix.sync.aligned.m8n8.x4.shared.b16 {%0,%1,%2,%3}, [%4];" \
                 : "=r"((r)[0]), "=r"((r)[1]), "=r"((r)[2]), "=r"((r)[3]) : "r"(a))

#define MMA_BF16(d, a, b0, b1)                                                 \
    asm volatile(                                                              \
        "mma.sync.aligned.m16n8k16.row.col.f32.bf16.bf16.f32 "                 \
        "{%0,%1,%2,%3},{%4,%5,%6,%7},{%8,%9},{%0,%1,%2,%3};"                   \
        : "+f"((d)[0]), "+f"((d)[1]), "+f"((d)[2]), "+f"((d)[3])               \
        : "r"((a)[0]), "r"((a)[1]), "r"((a)[2]), "r"((a)[3]), "r"(b0), "r"(b1))

__device__ __forceinline__ void split2(float a, float b, __nv_bfloat162& hi,
                                       __nv_bfloat162& lo) {
    hi = __floats2bfloat162_rn(a, b);
    lo = __floats2bfloat162_rn(a - __bfloat162float(hi.x), b - __bfloat162float(hi.y));
}

// ============================================================================
// Generic bf16-split GEMM (3-stage cp.async): C[m,n] (+)= sum_p A[m+sh_p,:]Wp[n,:]
// flags: 1=addBias, 2=accumulate fp32, 4=split bf16 out.
// ============================================================================
#define STAGE_B 65536
#define GSMEM (3 * STAGE_B)

__global__ __launch_bounds__(256, 1)
void mma_gemm_k(const __nv_bfloat16* __restrict__ Ah, const __nv_bfloat16* __restrict__ Al,
                const __nv_bfloat16* __restrict__ Wh, const __nv_bfloat16* __restrict__ Wl,
                const float* __restrict__ bias, float* __restrict__ Cf,
                __nv_bfloat16* __restrict__ Ch, __nv_bfloat16* __restrict__ Cl,
                int N, int nPasses, int s0, int s1, int s2, int flags) {
    extern __shared__ char smem[];
    const uint32_t smb = smem_u32(smem);
    const int tid = threadIdx.x, lane = tid & 31, wid = tid >> 5;
    const int mBase = blockIdx.y << 7, nBase = blockIdx.x << 7;
    const int wm = wid & 3, wn = wid >> 2;

    float acc[2][8][4];
#pragma unroll
    for (int t = 0; t < 2; t++)
#pragma unroll
        for (int j = 0; j < 8; j++)
#pragma unroll
            for (int q = 0; q < 4; q++) acc[t][j][q] = 0.f;

    const int total = nPasses * 8;
    const int rBase = tid >> 3, col16 = tid & 7;

    auto issue = [&](int idx) {
        const int p = idx >> 3, c8 = idx & 7;
        const int shift = (p == 0) ? s0 : ((p == 1) ? s1 : s2);
        const size_t wOff = (size_t)p * DD;
        const uint32_t sb = smb + (uint32_t)(idx % 3) * STAGE_B;
        const int kOff = c8 * 64 + col16 * 8;
#pragma unroll
        for (int c = 0; c < 4; c++) {
            const int row = rBase + c * 32;
            const uint32_t dsw = swz((uint32_t)(row * 128 + col16 * 16));
            const int m = mBase + row;
            const int l = m & (Lsz - 1);
            const bool valid = ((unsigned)(l + shift) < (unsigned)Lsz);
            const size_t aoff = (size_t)(m + (valid ? shift : 0)) * Dsz + kOff;
            cp16(sb + dsw, Ah + aoff, valid);
            cp16(sb + 16384 + dsw, Al + aoff, valid);
            const size_t woff = wOff + (size_t)(nBase + row) * Dsz + kOff;
            cp16(sb + 32768 + dsw, Wh + woff, true);
            cp16(sb + 49152 + dsw, Wl + woff, true);
        }
        CP_COMMIT();
    };

    issue(0);
    if (total > 1) issue(1);
    for (int idx = 0; idx < total; idx++) {
        if (idx + 2 < total) {
            issue(idx + 2);
            asm volatile("cp.async.wait_group 2;" ::: "memory");
        } else if (idx + 1 < total) {
            asm volatile("cp.async.wait_group 1;" ::: "memory");
        } else {
            asm volatile("cp.async.wait_group 0;" ::: "memory");
        }
        __syncthreads();
        const uint32_t sb = smb + (uint32_t)(idx % 3) * STAGE_B;
#pragma unroll
        for (int kk = 0; kk < 4; kk++) {
            uint32_t ah[2][4], al[2][4];
#pragma unroll
            for (int t = 0; t < 2; t++) {
                const int row = wm * 32 + t * 16 + (lane & 15);
                const uint32_t off =
                    swz((uint32_t)(row * 128 + kk * 32 + (lane >> 4) * 16));
                LDSM_X4(ah[t], sb + off);
                LDSM_X4(al[t], sb + 16384 + off);
            }
#pragma unroll
            for (int jp = 0; jp < 4; jp++) {
                const int nrow = wn * 64 + jp * 16 + (lane & 7) + ((lane >> 4) << 3);
                const uint32_t off =
                    swz((uint32_t)(nrow * 128 + kk * 32 + ((lane >> 3) & 1) * 16));
                uint32_t bh[4], bl[4];
                LDSM_X4(bh, sb + 32768 + off);
                LDSM_X4(bl, sb + 49152 + off);
#pragma unroll
                for (int t = 0; t < 2; t++) {
#pragma unroll
                    for (int jj = 0; jj < 2; jj++) {
                        float* d = acc[t][jp * 2 + jj];
                        MMA_BF16(d, ah[t], bh[jj * 2], bh[jj * 2 + 1]);
                        MMA_BF16(d, ah[t], bl[jj * 2], bl[jj * 2 + 1]);
                        MMA_BF16(d, al[t], bh[jj * 2], bh[jj * 2 + 1]);
                    }
                }
            }
        }
        __syncthreads();
    }

    const bool addB = (flags & 1) != 0;
    const bool accum = (flags & 2) != 0;
    const bool splitO = (flags & 4) != 0;
#pragma unroll
    for (int t = 0; t < 2; t++) {
#pragma unroll
        for (int j = 0; j < 8; j++) {
            const int r0 = mBase + wm * 32 + t * 16 + (lane >> 2);
            const int col = nBase + wn * 64 + j * 8 + (lane & 3) * 2;
            float b0 = 0.f, b1 = 0.f;
            if (addB) { b0 = bias[col]; b1 = bias[col + 1]; }
            float v0 = acc[t][j][0] + b0, v1 = acc[t][j][1] + b1;
            float v2 = acc[t][j][2] + b0, v3 = acc[t][j][3] + b1;
            const size_t o0 = (size_t)r0 * N + col;
            const size_t o1 = (size_t)(r0 + 8) * N + col;
            if (splitO) {
                __nv_bfloat162 h, lo;
                split2(v0, v1, h, lo);
                *(__nv_bfloat162*)(Ch + o0) = h;
                *(__nv_bfloat162*)(Cl + o0) = lo;
                split2(v2, v3, h, lo);
                *(__nv_bfloat162*)(Ch + o1) = h;
                *(__nv_bfloat162*)(Cl + o1) = lo;
            } else {
                if (accum) {
                    float2 p0 = *(float2*)(Cf + o0);
                    float2 p1 = *(float2*)(Cf + o1);
                    v0 += p0.x; v1 += p0.y; v2 += p1.x; v3 += p1.y;
                }
                *(float2*)(Cf + o0) = make_float2(v0, v1);
                *(float2*)(Cf + o1) = make_float2(v2, v3);
            }
        }
    }
}

// ============================================================================
// Fused fc + gated-MLP GEMM: computes gate = A·Wg^T + bg, val = A·Wv^T + bv,
// writes split-bf16 of sigmoid(gate)*val. Wg = fc rows [0,512), Wv = [512,1024).
// ============================================================================
#define FC_STAGE 98304
#define FCSMEM (2 * FC_STAGE)

__global__ __launch_bounds__(256, 1)
void mma_fc_k(const __nv_bfloat16* __restrict__ Ah, const __nv_bfloat16* __restrict__ Al,
              const __nv_bfloat16* __restrict__ Wh, const __nv_bfloat16* __restrict__ Wl,
              const float* __restrict__ bias,
              __nv_bfloat16* __restrict__ Oh, __nv_bfloat16* __restrict__ Ol) {
    extern __shared__ char smem[];
    const uint32_t smb = smem_u32(smem);
    const int tid = threadIdx.x, lane = tid & 31, wid = tid >> 5;
    const int mBase = blockIdx.y << 7, nBase = blockIdx.x << 7;
    const int wm = wid & 3, wn = wid >> 2;

    float accg[2][8][4], accv[2][8][4];
#pragma unroll
    for (int t = 0; t < 2; t++)
#pragma unroll
        for (int j = 0; j < 8; j++)
#pragma unroll
            for (int q = 0; q < 4; q++) { accg[t][j][q] = 0.f; accv[t][j][q] = 0.f; }

    const int rBase = tid >> 3, col16 = tid & 7;

    auto issue = [&](int idx) {
        const int c8 = idx & 7;
        const uint32_t sb = smb + (uint32_t)(idx & 1) * FC_STAGE;
        const int kOff = c8 * 64 + col16 * 8;
#pragma unroll
        for (int c = 0; c < 4; c++) {
            const int row = rBase + c * 32;
            const uint32_t dsw = swz((uint32_t)(row * 128 + col16 * 16));
            const size_t aoff = (size_t)(mBase + row) * Dsz + kOff;
            cp16(sb + dsw, Ah + aoff, true);
            cp16(sb + 16384 + dsw, Al + aoff, true);
            const size_t wgoff = (size_t)(nBase + row) * Dsz + kOff;
            cp16(sb + 32768 + dsw, Wh + wgoff, true);
            cp16(sb + 49152 + dsw, Wl + wgoff, true);
            const size_t wvoff = (size_t)(512 + nBase + row) * Dsz + kOff;
            cp16(sb + 65536 + dsw, Wh + wvoff, true);
            cp16(sb + 81920 + dsw, Wl + wvoff, true);
        }
        CP_COMMIT();
    };

    issue(0);
    for (int idx = 0; idx < 8; idx++) {
        if (idx + 1 < 8) {
            issue(idx + 1);
            asm volatile("cp.async.wait_group 1;" ::: "memory");
        } else {
            asm volatile("cp.async.wait_group 0;" ::: "memory");
        }
        __syncthreads();
        const uint32_t sb = smb + (uint32_t)(idx & 1) * FC_STAGE;
#pragma unroll
        for (int kk = 0; kk < 4; kk++) {
            uint32_t ah[2][4], al[2][4];
#pragma unroll
            for (int t = 0; t < 2; t++) {
                const int row = wm * 32 + t * 16 + (lane & 15);
                const uint32_t off =
                    swz((uint32_t)(row * 128 + kk * 32 + (lane >> 4) * 16));
                LDSM_X4(ah[t], sb + off);
                LDSM_X4(al[t], sb + 16384 + off);
            }
#pragma unroll
            for (int jp = 0; jp < 4; jp++) {
                const int nrow = wn * 64 + jp * 16 + (lane & 7) + ((lane >> 4) << 3);
                const uint32_t off =
                    swz((uint32_t)(nrow * 128 + kk * 32 + ((lane >> 3) & 1) * 16));
                {
                    uint32_t bh[4], bl[4];
                    LDSM_X4(bh, sb + 32768 + off);
                    LDSM_X4(bl, sb + 49152 + off);
#pragma unroll
                    for (int t = 0; t < 2; t++)
#pragma unroll
                        for (int jj = 0; jj < 2; jj++) {
                            float* d = accg[t][jp * 2 + jj];
                            MMA_BF16(d, ah[t], bh[jj * 2], bh[jj * 2 + 1]);
                            MMA_BF16(d, ah[t], bl[jj * 2], bl[jj * 2 + 1]);
                            MMA_BF16(d, al[t], bh[jj * 2], bh[jj * 2 + 1]);
                        }
                }
                {
                    uint32_t bh[4], bl[4];
                    LDSM_X4(bh, sb + 65536 + off);
                    LDSM_X4(bl, sb + 81920 + off);
#pragma unroll
                    for (int t = 0; t < 2; t++)
#pragma unroll
                        for (int jj = 0; jj < 2; jj++) {
                            float* d = accv[t][jp * 2 + jj];
                            MMA_BF16(d, ah[t], bh[jj * 2], bh[jj * 2 + 1]);
                            MMA_BF16(d, ah[t], bl[jj * 2], bl[jj * 2 + 1]);
                            MMA_BF16(d, al[t], bh[jj * 2], bh[jj * 2 + 1]);
                        }
                }
            }
        }
        __syncthreads();
    }

#pragma unroll
    for (int t = 0; t < 2; t++) {
#pragma unroll
        for (int j = 0; j < 8; j++) {
            const int r0 = mBase + wm * 32 + t * 16 + (lane >> 2);
            const int col = nBase + wn * 64 + j * 8 + (lane & 3) * 2;
            const float bg0 = bias[col], bg1 = bias[col + 1];
            const float bv0 = bias[512 + col], bv1 = bias[512 + col + 1];
            float s0 = 1.f / (1.f + expf(-(accg[t][j][0] + bg0)));
            float s1 = 1.f / (1.f + expf(-(accg[t][j][1] + bg1)));
            float s2 = 1.f / (1.f + expf(-(accg[t][j][2] + bg0)));
            float s3 = 1.f / (1.f + expf(-(accg[t][j][3] + bg1)));
            float v0 = s0 * (accv[t][j][0] + bv0);
            float v1 = s1 * (accv[t][j][1] + bv1);
            float v2 = s2 * (accv[t][j][2] + bv0);
            float v3 = s3 * (accv[t][j][3] + bv1);
            const size_t o0 = (size_t)r0 * Dsz + col;
            const size_t o1 = (size_t)(r0 + 8) * Dsz + col;
            __nv_bfloat162 h, lo;
            split2(v0, v1, h, lo);
            *(__nv_bfloat162*)(Oh + o0) = h;
            *(__nv_bfloat162*)(Ol + o0) = lo;
            split2(v2, v3, h, lo);
            *(__nv_bfloat162*)(Oh + o1) = h;
            *(__nv_bfloat162*)(Ol + o1) = lo;
        }
    }
}

// ---------------- embed: one-hot --------------------------------------------
__global__ void embed_k(const int* __restrict__ x, float* __restrict__ y) {
    int idx = blockIdx.x * blockDim.x + threadIdx.x;
    int t = idx >> 9, d = idx & 511;
    y[idx] = (x[t] == d) ? 1.0f : 0.0f;
}

// ---------------- layernorm with fused bf16 hi/lo split ----------------------
__global__ void ln_split_k(const float* __restrict__ in,
                           __nv_bfloat16* __restrict__ oh, __nv_bfloat16* __restrict__ ol,
                           const float* __restrict__ gamma, const float* __restrict__ beta) {
    int t = blockIdx.x, tid = threadIdx.x;
    const float4* rp = (const float4*)(in + (size_t)t * Dsz);
    float4 v = rp[tid];
    float s = v.x + v.y + v.z + v.w;
#pragma unroll
    for (int o = 16; o; o >>= 1) s += __shfl_xor_sync(0xffffffffu, s, o);
    __shared__ float smr[4];
    if ((tid & 31) == 0) smr[tid >> 5] = s;
    __syncthreads();
    float mean = (smr[0] + smr[1] + smr[2] + smr[3]) * (1.0f / Dsz);
    float dx = v.x - mean, dy = v.y - mean, dz = v.z - mean, dw = v.w - mean;
    float q = dx * dx + dy * dy + dz * dz + dw * dw;
#pragma unroll
    for (int o = 16; o; o >>= 1) q += __shfl_xor_sync(0xffffffffu, q, o);
    __syncthreads();
    if ((tid & 31) == 0) smr[tid >> 5] = q;
    __syncthreads();
    float var = (smr[0] + smr[1] + smr[2] + smr[3]) * (1.0f / Dsz);
    float rstd = rsqrtf(var + 1e-5f);
    float4 g4 = ((const float4*)gamma)[tid];
    float4 b4 = ((const float4*)beta)[tid];
    float f0 = dx * rstd * g4.x + b4.x, f1 = dy * rstd * g4.y + b4.y;
    float f2 = dz * rstd * g4.z + b4.z, f3 = dw * rstd * g4.w + b4.w;
    __nv_bfloat162 h01, l01, h23, l23;
    split2(f0, f1, h01, l01);
    split2(f2, f3, h23, l23);
    __nv_bfloat162* ph = (__nv_bfloat162*)(oh + (size_t)t * Dsz);
    __nv_bfloat162* pl = (__nv_bfloat162*)(ol + (size_t)t * Dsz);
    ph[2 * tid] = h01; ph[2 * tid + 1] = h23;
    pl[2 * tid] = l01; pl[2 * tid + 1] = l23;
}

// ---------------- conv weight repack + split (all layers) --------------------
__global__ void cwsplit_k(const float* __restrict__ cw,
                          __nv_bfloat16* __restrict__ wh, __nv_bfloat16* __restrict__ wl) {
    int idx = blockIdx.x * blockDim.x + threadIdx.x;  // over NL*3*DD
    int layer = idx / (3 * DD);
    int r = idx - layer * (3 * DD);
    int h = r / DD;
    int rr = r - h * DD;
    int o = rr >> 9, i = rr & 511;
    float v = cw[(size_t)layer * 3 * DD + ((size_t)o * Dsz + i) * 3 + h];
    __nv_bfloat16 hi = __float2bfloat16(v);
    wh[idx] = hi;
    wl[idx] = __float2bfloat16(v - __bfloat162float(hi));
}

// ---------------- generic weight split ---------------------------------------
__global__ void wsplit_k(const float* __restrict__ w, __nv_bfloat16* __restrict__ wh,
                         __nv_bfloat16* __restrict__ wl, int n) {
    int idx = blockIdx.x * blockDim.x + threadIdx.x;
    if (idx >= n) return;
    float v = w[idx];
    __nv_bfloat16 hi = __float2bfloat16(v);
    wh[idx] = hi;
    wl[idx] = __float2bfloat16(v - __bfloat162float(hi));
}

// ---------------- scalar gate -------------------------------------------------
__global__ void gate_k(const float* __restrict__ z, const float* __restrict__ wg,
                       const float* __restrict__ bg, float* __restrict__ gout) {
    int warp = (blockIdx.x * blockDim.x + threadIdx.x) >> 5;
    int lane = threadIdx.x & 31;
    const float4* row = (const float4*)(z + (size_t)warp * Dsz);
    const float4* w = (const float4*)wg;
    float s = 0.f;
#pragma unroll
    for (int i = 0; i < 4; i++) {
        float4 a = row[lane + 32 * i];
        float4 b = w[lane + 32 * i];
        s += a.x * b.x + a.y * b.y + a.z * b.z + a.w * b.w;
    }
#pragma unroll
    for (int o = 16; o; o >>= 1) s += __shfl_xor_sync(0xffffffffu, s, o);
    if (lane == 0) gout[warp] = 1.0f / (1.0f + expf(-(s + bg[0])));
}

// ---------------- sequential scan, split output --------------------------------
__global__ void scan_split_k(const float* __restrict__ x, const float* __restrict__ g,
                             __nv_bfloat16* __restrict__ hh, __nv_bfloat16* __restrict__ hl) {
    int b = blockIdx.x >> 2;
    int d = ((blockIdx.x & 3) << 7) + threadIdx.x;
    size_t base = (size_t)b * Lsz * Dsz + d;
    const float* gb = g + (size_t)b * Lsz;
    float hv = 0.f;
    for (int l = 0; l < Lsz; l += 8) {
        float xs[8], gs[8];
#pragma unroll
        for (int j = 0; j < 8; j++) {
            xs[j] = x[base + (size_t)(l + j) * Dsz];
            gs[j] = gb[l + j];
        }
#pragma unroll
        for (int j = 0; j < 8; j++) {
            hv = fmaf(gs[j], xs[j] - hv, hv);
            __nv_bfloat16 hi = __float2bfloat16(hv);
            size_t o = base + (size_t)(l + j) * Dsz;
            hh[o] = hi;
            hl[o] = __float2bfloat16(hv - __bfloat162float(hi));
        }
    }
}

// ---------------- launch --------------------------------------------------------
extern "C" void kernel_launch(void* const* d_in, const int* in_sizes, int n_in,
                              void* d_out, int out_size) {
    const int* x = (const int*)d_in[0];
    const float* ln_g = (const float*)d_in[1];
    const float* ln_b = (const float*)d_in[2];
    const float* conv_w = (const float*)d_in[3];
    const float* conv_b = (const float*)d_in[4];
    const float* wg = (const float*)d_in[5];
    const float* bg = (const float*)d_in[6];
    const float* wout = (const float*)d_in[7];
    const float* bout = (const float*)d_in[8];
    const float* fc_w = (const float*)d_in[9];
    const float* fc_b = (const float*)d_in[10];
    const float* mo_w = (const float*)d_in[11];
    const float* mo_b = (const float*)d_in[12];
    const float* lnf_g = (const float*)d_in[13];
    const float* lnf_b = (const float*)d_in[14];
    const float* head_w = (const float*)d_in[15];
    const float* head_b = (const float*)d_in[16];

    float *y, *z2, *gt;
    __nv_bfloat16 *zh, *zl, *hh, *hl, *gh, *gl, *wh, *wl;
    cudaGetSymbolAddress((void**)&y, g_y);
    cudaGetSymbolAddress((void**)&z2, g_z2);
    cudaGetSymbolAddress((void**)&gt, g_gate);
    cudaGetSymbolAddress((void**)&zh, g_zh);
    cudaGetSymbolAddress((void**)&zl, g_zl);
    cudaGetSymbolAddress((void**)&hh, g_hh);
    cudaGetSymbolAddress((void**)&hl, g_hl);
    cudaGetSymbolAddress((void**)&gh, g_gh);
    cudaGetSymbolAddress((void**)&gl, g_gl);
    cudaGetSymbolAddress((void**)&wh, g_wh);
    cudaGetSymbolAddress((void**)&wl, g_wl);

    cudaFuncSetAttribute(mma_gemm_k, cudaFuncAttributeMaxDynamicSharedMemorySize, GSMEM);
    cudaFuncSetAttribute(mma_fc_k, cudaFuncAttributeMaxDynamicSharedMemorySize, FCSMEM);

    const dim3 g512(4, Tsz / 128);

    // ---- one-time work (per call): embed + all weight splits ----
    embed_k<<<(Tsz * Dsz) / 256, 256>>>(x, y);
    cwsplit_k<<<(NLsz * 3 * DD) / 256, 256>>>(conv_w, wh + W_CONV(0), wl + W_CONV(0));
    wsplit_k<<<(NLsz * DD) / 256, 256>>>(wout, wh + W_WOUT(0), wl + W_WOUT(0), NLsz * DD);
    wsplit_k<<<(NLsz * 2 * DD) / 256, 256>>>(fc_w, wh + W_FC(0), wl + W_FC(0), NLsz * 2 * DD);
    wsplit_k<<<(NLsz * DD) / 256, 256>>>(mo_w, wh + W_MO(0), wl + W_MO(0), NLsz * DD);
    wsplit_k<<<DD / 256, 256>>>(head_w, wh + W_HEAD, wl + W_HEAD, DD);

    for (int i = 0; i < NLsz; i++) {
        ln_split_k<<<Tsz, 128>>>(y, zh, zl, ln_g + (size_t)i * Dsz, ln_b + (size_t)i * Dsz);
        // conv: 3 shifted passes accumulated in registers
        mma_gemm_k<<<g512, 256, GSMEM>>>(zh, zl, wh + W_CONV(i), wl + W_CONV(i),
                                         conv_b + (size_t)i * Dsz, z2, nullptr, nullptr,
                                         Dsz, 3, -1, 0, 1, 1);
        gate_k<<<Tsz / 4, 128>>>(z2, wg + (size_t)i * Dsz, bg + i, gt);
        scan_split_k<<<64, 128>>>(z2, gt, hh, hl);
        // wout: split-bf16 output into zh/zl
        mma_gemm_k<<<g512, 256, GSMEM>>>(hh, hl, wh + W_WOUT(i), wl + W_WOUT(i),
                                         bout + (size_t)i * Dsz, nullptr, zh, zl,
                                         Dsz, 1, 0, 0, 0, 5);
        // fc + gated-MLP fused, split-bf16 out
        mma_fc_k<<<g512, 256, FCSMEM>>>(zh, zl, wh + W_FC(i), wl + W_FC(i),
                                        fc_b + (size_t)i * 2 * Dsz, gh, gl);
        // mo with residual accumulate into y
        mma_gemm_k<<<g512, 256, GSMEM>>>(gh, gl, wh + W_MO(i), wl + W_MO(i),
                                         mo_b + (size_t)i * Dsz, y, nullptr, nullptr,
                                         Dsz, 1, 0, 0, 0, 3);
    }

    ln_split_k<<<Tsz, 128>>>(y, zh, zl, lnf_g, lnf_b);
    mma_gemm_k<<<g512, 256, GSMEM>>>(zh, zl, wh + W_HEAD, wl + W_HEAD, head_b,
                                     (float*)d_out, nullptr, nullptr, Dsz, 1, 0, 0, 0, 1);
}

// round 5
// speedup vs baseline: 2.6963x; 1.0865x over previous
#include <cuda_runtime.h>
#include <cuda_bf16.h>
#include <cstdint>
#include <cstddef>

#define Bsz 16
#define Lsz 2048
#define Dsz 512
#define NLsz 4
#define Tsz (Bsz * Lsz)  // 32768
#define DD (Dsz * Dsz)

// weight arena offsets (units of DD)
#define W_CONV(i) ((size_t)(i) * 3 * DD)
#define W_WOUT(i) ((size_t)(12 + (i)) * DD)
#define W_FC(i)   ((size_t)(16 + 2 * (i)) * DD)
#define W_MO(i)   ((size_t)(24 + (i)) * DD)
#define W_HEAD    ((size_t)28 * DD)

// scan chunking
#define SCH 256                 // steps per chunk
#define NCH (Lsz / SCH)         // 8 chunks

// ---------------- scratch (device globals; no allocation allowed) ----------
__device__ float g_y[Tsz * Dsz];          // residual (fp32)
__device__ float g_z2[Tsz * Dsz];         // conv out (fp32)
__device__ float g_gate[Tsz];
__device__ float g_hend[NCH * Bsz * Dsz];   // scan: chunk-end h
__device__ float g_aprod[NCH * Bsz * Dsz];  // scan: chunk decay product
__device__ float g_carry[NCH * Bsz * Dsz];  // scan: chunk-entry carry
__device__ __nv_bfloat16 g_zh[Tsz * Dsz], g_zl[Tsz * Dsz];
__device__ __nv_bfloat16 g_hh[Tsz * Dsz], g_hl[Tsz * Dsz];
__device__ __nv_bfloat16 g_gh[Tsz * Dsz], g_gl[Tsz * Dsz];
__device__ __nv_bfloat16 g_wh[29 * DD], g_wl[29 * DD];

// ---------------- helpers ---------------------------------------------------
__device__ __forceinline__ uint32_t smem_u32(const void* p) {
    return (uint32_t)__cvta_generic_to_shared(p);
}
__device__ __forceinline__ uint32_t swz(uint32_t x) { return x ^ ((x >> 3) & 0x70); }

__device__ __forceinline__ void cp16(uint32_t dst, const void* src, bool v) {
    int sz = v ? 16 : 0;
    asm volatile("cp.async.cg.shared.global [%0], [%1], 16, %2;"
                 :: "r"(dst), "l"(src), "r"(sz) : "memory");
}
#define CP_COMMIT() asm volatile("cp.async.commit_group;" ::: "memory")

#define LDSM_X4(r, a)                                                          \
    asm volatile("ldmatrix.sync.aligned.m8n8.x4.shared.b16 {%0,%1,%2,%3}, [%4];" \
                 : "=r"((r)[0]), "=r"((r)[1]), "=r"((r)[2]), "=r"((r)[3]) : "r"(a))

#define MMA_BF16(d, a, b0, b1)                                                 \
    asm volatile(                                                              \
        "mma.sync.aligned.m16n8k16.row.col.f32.bf16.bf16.f32 "                 \
        "{%0,%1,%2,%3},{%4,%5,%6,%7},{%8,%9},{%0,%1,%2,%3};"                   \
        : "+f"((d)[0]), "+f"((d)[1]), "+f"((d)[2]), "+f"((d)[3])               \
        : "r"((a)[0]), "r"((a)[1]), "r"((a)[2]), "r"((a)[3]), "r"(b0), "r"(b1))

__device__ __forceinline__ void split2(float a, float b, __nv_bfloat162& hi,
                                       __nv_bfloat162& lo) {
    hi = __floats2bfloat162_rn(a, b);
    lo = __floats2bfloat162_rn(a - __bfloat162float(hi.x), b - __bfloat162float(hi.y));
}

// ============================================================================
// Generic bf16-split GEMM, 512 threads, tile 128x128, 16 warps (4Mx4N, 32x32).
// flags: 1=addBias, 2=accumulate fp32, 4=split bf16 out.
// ============================================================================
#define STAGE_B 65536
#define GSMEM (3 * STAGE_B)

__global__ __launch_bounds__(512, 1)
void mma_gemm_k(const __nv_bfloat16* __restrict__ Ah, const __nv_bfloat16* __restrict__ Al,
                const __nv_bfloat16* __restrict__ Wh, const __nv_bfloat16* __restrict__ Wl,
                const float* __restrict__ bias, float* __restrict__ Cf,
                __nv_bfloat16* __restrict__ Ch, __nv_bfloat16* __restrict__ Cl,
                int N, int nPasses, int s0, int s1, int s2, int flags) {
    extern __shared__ char smem[];
    const uint32_t smb = smem_u32(smem);
    const int tid = threadIdx.x, lane = tid & 31, wid = tid >> 5;
    const int mBase = blockIdx.y << 7, nBase = blockIdx.x << 7;
    const int wm = wid & 3, wn = wid >> 2;

    float acc[2][4][4];
#pragma unroll
    for (int t = 0; t < 2; t++)
#pragma unroll
        for (int j = 0; j < 4; j++)
#pragma unroll
            for (int q = 0; q < 4; q++) acc[t][j][q] = 0.f;

    const int total = nPasses * 8;
    const int rowIdx = tid >> 3, col16 = tid & 7;

    auto issue = [&](int idx) {
        const int p = idx >> 3, c8 = idx & 7;
        const int shift = (p == 0) ? s0 : ((p == 1) ? s1 : s2);
        const size_t wOff = (size_t)p * DD;
        const uint32_t sb = smb + (uint32_t)(idx % 3) * STAGE_B;
        const int kOff = c8 * 64 + col16 * 8;
#pragma unroll
        for (int c = 0; c < 2; c++) {
            const int row = rowIdx + c * 64;
            const uint32_t dsw = swz((uint32_t)(row * 128 + col16 * 16));
            const int m = mBase + row;
            const int l = m & (Lsz - 1);
            const bool valid = ((unsigned)(l + shift) < (unsigned)Lsz);
            const size_t aoff = (size_t)(m + (valid ? shift : 0)) * Dsz + kOff;
            cp16(sb + dsw, Ah + aoff, valid);
            cp16(sb + 16384 + dsw, Al + aoff, valid);
            const size_t woff = wOff + (size_t)(nBase + row) * Dsz + kOff;
            cp16(sb + 32768 + dsw, Wh + woff, true);
            cp16(sb + 49152 + dsw, Wl + woff, true);
        }
        CP_COMMIT();
    };

    issue(0);
    if (total > 1) issue(1);
    for (int idx = 0; idx < total; idx++) {
        if (idx + 2 < total) {
            issue(idx + 2);
            asm volatile("cp.async.wait_group 2;" ::: "memory");
        } else if (idx + 1 < total) {
            asm volatile("cp.async.wait_group 1;" ::: "memory");
        } else {
            asm volatile("cp.async.wait_group 0;" ::: "memory");
        }
        __syncthreads();
        const uint32_t sb = smb + (uint32_t)(idx % 3) * STAGE_B;
#pragma unroll
        for (int kk = 0; kk < 4; kk++) {
            uint32_t ah[2][4], al[2][4];
#pragma unroll
            for (int t = 0; t < 2; t++) {
                const int row = wm * 32 + t * 16 + (lane & 15);
                const uint32_t off =
                    swz((uint32_t)(row * 128 + kk * 32 + (lane >> 4) * 16));
                LDSM_X4(ah[t], sb + off);
                LDSM_X4(al[t], sb + 16384 + off);
            }
#pragma unroll
            for (int jp = 0; jp < 2; jp++) {
                const int nrow = wn * 32 + jp * 16 + (lane & 7) + ((lane >> 4) << 3);
                const uint32_t off =
                    swz((uint32_t)(nrow * 128 + kk * 32 + ((lane >> 3) & 1) * 16));
                uint32_t bh[4], bl[4];
                LDSM_X4(bh, sb + 32768 + off);
                LDSM_X4(bl, sb + 49152 + off);
#pragma unroll
                for (int t = 0; t < 2; t++) {
#pragma unroll
                    for (int jj = 0; jj < 2; jj++) {
                        float* d = acc[t][jp * 2 + jj];
                        MMA_BF16(d, ah[t], bh[jj * 2], bh[jj * 2 + 1]);
                        MMA_BF16(d, ah[t], bl[jj * 2], bl[jj * 2 + 1]);
                        MMA_BF16(d, al[t], bh[jj * 2], bh[jj * 2 + 1]);
                    }
                }
            }
        }
        __syncthreads();
    }

    const bool addB = (flags & 1) != 0;
    const bool accum = (flags & 2) != 0;
    const bool splitO = (flags & 4) != 0;
#pragma unroll
    for (int t = 0; t < 2; t++) {
#pragma unroll
        for (int j = 0; j < 4; j++) {
            const int r0 = mBase + wm * 32 + t * 16 + (lane >> 2);
            const int col = nBase + wn * 32 + j * 8 + (lane & 3) * 2;
            float b0 = 0.f, b1 = 0.f;
            if (addB) { b0 = bias[col]; b1 = bias[col + 1]; }
            float v0 = acc[t][j][0] + b0, v1 = acc[t][j][1] + b1;
            float v2 = acc[t][j][2] + b0, v3 = acc[t][j][3] + b1;
            const size_t o0 = (size_t)r0 * N + col;
            const size_t o1 = (size_t)(r0 + 8) * N + col;
            if (splitO) {
                __nv_bfloat162 h, lo;
                split2(v0, v1, h, lo);
                *(__nv_bfloat162*)(Ch + o0) = h;
                *(__nv_bfloat162*)(Cl + o0) = lo;
                split2(v2, v3, h, lo);
                *(__nv_bfloat162*)(Ch + o1) = h;
                *(__nv_bfloat162*)(Cl + o1) = lo;
            } else {
                if (accum) {
                    float2 p0 = *(float2*)(Cf + o0);
                    float2 p1 = *(float2*)(Cf + o1);
                    v0 += p0.x; v1 += p0.y; v2 += p1.x; v3 += p1.y;
                }
                *(float2*)(Cf + o0) = make_float2(v0, v1);
                *(float2*)(Cf + o1) = make_float2(v2, v3);
            }
        }
    }
}

// ============================================================================
// Fused fc + gated-MLP GEMM, 512 threads: gate/val tiles share the A stage,
// epilogue writes split-bf16 of sigmoid(gate)*val.
// ============================================================================
#define FC_STAGE 98304
#define FCSMEM (2 * FC_STAGE)

__global__ __launch_bounds__(512, 1)
void mma_fc_k(const __nv_bfloat16* __restrict__ Ah, const __nv_bfloat16* __restrict__ Al,
              const __nv_bfloat16* __restrict__ Wh, const __nv_bfloat16* __restrict__ Wl,
              const float* __restrict__ bias,
              __nv_bfloat16* __restrict__ Oh, __nv_bfloat16* __restrict__ Ol) {
    extern __shared__ char smem[];
    const uint32_t smb = smem_u32(smem);
    const int tid = threadIdx.x, lane = tid & 31, wid = tid >> 5;
    const int mBase = blockIdx.y << 7, nBase = blockIdx.x << 7;
    const int wm = wid & 3, wn = wid >> 2;

    float accg[2][4][4], accv[2][4][4];
#pragma unroll
    for (int t = 0; t < 2; t++)
#pragma unroll
        for (int j = 0; j < 4; j++)
#pragma unroll
            for (int q = 0; q < 4; q++) { accg[t][j][q] = 0.f; accv[t][j][q] = 0.f; }

    const int rowIdx = tid >> 3, col16 = tid & 7;

    auto issue = [&](int idx) {
        const int c8 = idx & 7;
        const uint32_t sb = smb + (uint32_t)(idx & 1) * FC_STAGE;
        const int kOff = c8 * 64 + col16 * 8;
#pragma unroll
        for (int c = 0; c < 2; c++) {
            const int row = rowIdx + c * 64;
            const uint32_t dsw = swz((uint32_t)(row * 128 + col16 * 16));
            const size_t aoff = (size_t)(mBase + row) * Dsz + kOff;
            cp16(sb + dsw, Ah + aoff, true);
            cp16(sb + 16384 + dsw, Al + aoff, true);
            const size_t wgoff = (size_t)(nBase + row) * Dsz + kOff;
            cp16(sb + 32768 + dsw, Wh + wgoff, true);
            cp16(sb + 49152 + dsw, Wl + wgoff, true);
            const size_t wvoff = (size_t)(512 + nBase + row) * Dsz + kOff;
            cp16(sb + 65536 + dsw, Wh + wvoff, true);
            cp16(sb + 81920 + dsw, Wl + wvoff, true);
        }
        CP_COMMIT();
    };

    issue(0);
    for (int idx = 0; idx < 8; idx++) {
        if (idx + 1 < 8) {
            issue(idx + 1);
            asm volatile("cp.async.wait_group 1;" ::: "memory");
        } else {
            asm volatile("cp.async.wait_group 0;" ::: "memory");
        }
        __syncthreads();
        const uint32_t sb = smb + (uint32_t)(idx & 1) * FC_STAGE;
#pragma unroll
        for (int kk = 0; kk < 4; kk++) {
            uint32_t ah[2][4], al[2][4];
#pragma unroll
            for (int t = 0; t < 2; t++) {
                const int row = wm * 32 + t * 16 + (lane & 15);
                const uint32_t off =
                    swz((uint32_t)(row * 128 + kk * 32 + (lane >> 4) * 16));
                LDSM_X4(ah[t], sb + off);
                LDSM_X4(al[t], sb + 16384 + off);
            }
#pragma unroll
            for (int jp = 0; jp < 2; jp++) {
                const int nrow = wn * 32 + jp * 16 + (lane & 7) + ((lane >> 4) << 3);
                const uint32_t off =
                    swz((uint32_t)(nrow * 128 + kk * 32 + ((lane >> 3) & 1) * 16));
                {
                    uint32_t bh[4], bl[4];
                    LDSM_X4(bh, sb + 32768 + off);
                    LDSM_X4(bl, sb + 49152 + off);
#pragma unroll
                    for (int t = 0; t < 2; t++)
#pragma unroll
                        for (int jj = 0; jj < 2; jj++) {
                            float* d = accg[t][jp * 2 + jj];
                            MMA_BF16(d, ah[t], bh[jj * 2], bh[jj * 2 + 1]);
                            MMA_BF16(d, ah[t], bl[jj * 2], bl[jj * 2 + 1]);
                            MMA_BF16(d, al[t], bh[jj * 2], bh[jj * 2 + 1]);
                        }
                }
                {
                    uint32_t bh[4], bl[4];
                    LDSM_X4(bh, sb + 65536 + off);
                    LDSM_X4(bl, sb + 81920 + off);
#pragma unroll
                    for (int t = 0; t < 2; t++)
#pragma unroll
                        for (int jj = 0; jj < 2; jj++) {
                            float* d = accv[t][jp * 2 + jj];
                            MMA_BF16(d, ah[t], bh[jj * 2], bh[jj * 2 + 1]);
                            MMA_BF16(d, ah[t], bl[jj * 2], bl[jj * 2 + 1]);
                            MMA_BF16(d, al[t], bh[jj * 2], bh[jj * 2 + 1]);
                        }
                }
            }
        }
        __syncthreads();
    }

#pragma unroll
    for (int t = 0; t < 2; t++) {
#pragma unroll
        for (int j = 0; j < 4; j++) {
            const int r0 = mBase + wm * 32 + t * 16 + (lane >> 2);
            const int col = nBase + wn * 32 + j * 8 + (lane & 3) * 2;
            const float bg0 = bias[col], bg1 = bias[col + 1];
            const float bv0 = bias[512 + col], bv1 = bias[512 + col + 1];
            float s0 = 1.f / (1.f + expf(-(accg[t][j][0] + bg0)));
            float s1 = 1.f / (1.f + expf(-(accg[t][j][1] + bg1)));
            float s2 = 1.f / (1.f + expf(-(accg[t][j][2] + bg0)));
            float s3 = 1.f / (1.f + expf(-(accg[t][j][3] + bg1)));
            float v0 = s0 * (accv[t][j][0] + bv0);
            float v1 = s1 * (accv[t][j][1] + bv1);
            float v2 = s2 * (accv[t][j][2] + bv0);
            float v3 = s3 * (accv[t][j][3] + bv1);
            const size_t o0 = (size_t)r0 * Dsz + col;
            const size_t o1 = (size_t)(r0 + 8) * Dsz + col;
            __nv_bfloat162 h, lo;
            split2(v0, v1, h, lo);
            *(__nv_bfloat162*)(Oh + o0) = h;
            *(__nv_bfloat162*)(Ol + o0) = lo;
            split2(v2, v3, h, lo);
            *(__nv_bfloat162*)(Oh + o1) = h;
            *(__nv_bfloat162*)(Ol + o1) = lo;
        }
    }
}

// ---------------- embed: one-hot --------------------------------------------
__global__ void embed_k(const int* __restrict__ x, float* __restrict__ y) {
    int idx = blockIdx.x * blockDim.x + threadIdx.x;
    int t = idx >> 9, d = idx & 511;
    y[idx] = (x[t] == d) ? 1.0f : 0.0f;
}

// ---------------- layer-0 LN: analytic LN of one-hot ------------------------
__global__ void ln0_split_k(const int* __restrict__ x,
                            __nv_bfloat16* __restrict__ oh, __nv_bfloat16* __restrict__ ol,
                            const float* __restrict__ gamma, const float* __restrict__ beta) {
    int t = blockIdx.x, tid = threadIdx.x;  // 128 thr, 4 d each
    const int tok = x[t];
    const float mean = 1.0f / 512.0f;
    const float var = (1.0f / 512.0f) * (511.0f / 512.0f);
    const float rstd = rsqrtf(var + 1e-5f);
    float4 g4 = ((const float4*)gamma)[tid];
    float4 b4 = ((const float4*)beta)[tid];
    int d0 = tid * 4;
    float f0 = (((d0 + 0) == tok ? 1.f : 0.f) - mean) * rstd * g4.x + b4.x;
    float f1 = (((d0 + 1) == tok ? 1.f : 0.f) - mean) * rstd * g4.y + b4.y;
    float f2 = (((d0 + 2) == tok ? 1.f : 0.f) - mean) * rstd * g4.z + b4.z;
    float f3 = (((d0 + 3) == tok ? 1.f : 0.f) - mean) * rstd * g4.w + b4.w;
    __nv_bfloat162 h01, l01, h23, l23;
    split2(f0, f1, h01, l01);
    split2(f2, f3, h23, l23);
    __nv_bfloat162* ph = (__nv_bfloat162*)(oh + (size_t)t * Dsz);
    __nv_bfloat162* pl = (__nv_bfloat162*)(ol + (size_t)t * Dsz);
    ph[2 * tid] = h01; ph[2 * tid + 1] = h23;
    pl[2 * tid] = l01; pl[2 * tid + 1] = l23;
}

// ---------------- layernorm with fused bf16 hi/lo split ----------------------
__global__ void ln_split_k(const float* __restrict__ in,
                           __nv_bfloat16* __restrict__ oh, __nv_bfloat16* __restrict__ ol,
                           const float* __restrict__ gamma, const float* __restrict__ beta) {
    int t = blockIdx.x, tid = threadIdx.x;
    const float4* rp = (const float4*)(in + (size_t)t * Dsz);
    float4 v = rp[tid];
    float s = v.x + v.y + v.z + v.w;
#pragma unroll
    for (int o = 16; o; o >>= 1) s += __shfl_xor_sync(0xffffffffu, s, o);
    __shared__ float smr[4];
    if ((tid & 31) == 0) smr[tid >> 5] = s;
    __syncthreads();
    float mean = (smr[0] + smr[1] + smr[2] + smr[3]) * (1.0f / Dsz);
    float dx = v.x - mean, dy = v.y - mean, dz = v.z - mean, dw = v.w - mean;
    float q = dx * dx + dy * dy + dz * dz + dw * dw;
#pragma unroll
    for (int o = 16; o; o >>= 1) q += __shfl_xor_sync(0xffffffffu, q, o);
    __syncthreads();
    if ((tid & 31) == 0) smr[tid >> 5] = q;
    __syncthreads();
    float var = (smr[0] + smr[1] + smr[2] + smr[3]) * (1.0f / Dsz);
    float rstd = rsqrtf(var + 1e-5f);
    float4 g4 = ((const float4*)gamma)[tid];
    float4 b4 = ((const float4*)beta)[tid];
    float f0 = dx * rstd * g4.x + b4.x, f1 = dy * rstd * g4.y + b4.y;
    float f2 = dz * rstd * g4.z + b4.z, f3 = dw * rstd * g4.w + b4.w;
    __nv_bfloat162 h01, l01, h23, l23;
    split2(f0, f1, h01, l01);
    split2(f2, f3, h23, l23);
    __nv_bfloat162* ph = (__nv_bfloat162*)(oh + (size_t)t * Dsz);
    __nv_bfloat162* pl = (__nv_bfloat162*)(ol + (size_t)t * Dsz);
    ph[2 * tid] = h01; ph[2 * tid + 1] = h23;
    pl[2 * tid] = l01; pl[2 * tid + 1] = l23;
}

// ---------------- conv weight repack + split (all layers) --------------------
__global__ void cwsplit_k(const float* __restrict__ cw,
                          __nv_bfloat16* __restrict__ wh, __nv_bfloat16* __restrict__ wl) {
    int idx = blockIdx.x * blockDim.x + threadIdx.x;
    int layer = idx / (3 * DD);
    int r = idx - layer * (3 * DD);
    int h = r / DD;
    int rr = r - h * DD;
    int o = rr >> 9, i = rr & 511;
    float v = cw[(size_t)layer * 3 * DD + ((size_t)o * Dsz + i) * 3 + h];
    __nv_bfloat16 hi = __float2bfloat16(v);
    wh[idx] = hi;
    wl[idx] = __float2bfloat16(v - __bfloat162float(hi));
}

// ---------------- generic weight split ---------------------------------------
__global__ void wsplit_k(const float* __restrict__ w, __nv_bfloat16* __restrict__ wh,
                         __nv_bfloat16* __restrict__ wl, int n) {
    int idx = blockIdx.x * blockDim.x + threadIdx.x;
    if (idx >= n) return;
    float v = w[idx];
    __nv_bfloat16 hi = __float2bfloat16(v);
    wh[idx] = hi;
    wl[idx] = __float2bfloat16(v - __bfloat162float(hi));
}

// ---------------- scalar gate -------------------------------------------------
__global__ void gate_k(const float* __restrict__ z, const float* __restrict__ wg,
                       const float* __restrict__ bg, float* __restrict__ gout) {
    int warp = (blockIdx.x * blockDim.x + threadIdx.x) >> 5;
    int lane = threadIdx.x & 31;
    const float4* row = (const float4*)(z + (size_t)warp * Dsz);
    const float4* w = (const float4*)wg;
    float s = 0.f;
#pragma unroll
    for (int i = 0; i < 4; i++) {
        float4 a = row[lane + 32 * i];
        float4 b = w[lane + 32 * i];
        s += a.x * b.x + a.y * b.y + a.z * b.z + a.w * b.w;
    }
#pragma unroll
    for (int o = 16; o; o >>= 1) s += __shfl_xor_sync(0xffffffffu, s, o);
    if (lane == 0) gout[warp] = 1.0f / (1.0f + expf(-(s + bg[0])));
}

// ---------------- chunked scan: phase 1 (local scan, no output) ---------------
__global__ void scan1_k(const float* __restrict__ x, const float* __restrict__ g,
                        float* __restrict__ hend, float* __restrict__ aprod) {
    int bx = blockIdx.x;                  // NCH*16*4 blocks
    int c = bx >> 6;
    int rem = bx & 63;
    int b = rem >> 2;
    int d = ((rem & 3) << 7) + threadIdx.x;
    size_t base = (size_t)b * Lsz * Dsz + d;
    const float* gb = g + (size_t)b * Lsz;
    const int l0 = c * SCH;
    float hv = 0.f, ap = 1.f;
    for (int l = l0; l < l0 + SCH; l += 8) {
        float xs[8], gs[8];
#pragma unroll
        for (int j = 0; j < 8; j++) {
            xs[j] = x[base + (size_t)(l + j) * Dsz];
            gs[j] = gb[l + j];
        }
#pragma unroll
        for (int j = 0; j < 8; j++) {
            hv = fmaf(gs[j], xs[j] - hv, hv);
            ap *= (1.f - gs[j]);
        }
    }
    const size_t o = (size_t)c * (Bsz * Dsz) + (size_t)b * Dsz + d;
    hend[o] = hv;
    aprod[o] = ap;
}

// ---------------- chunked scan: phase 2 (carry propagation) -------------------
__global__ void scan2_k(const float* __restrict__ hend, const float* __restrict__ aprod,
                        float* __restrict__ carry) {
    int lane = blockIdx.x * blockDim.x + threadIdx.x;  // 0..Bsz*Dsz-1
    float cv = 0.f;
#pragma unroll
    for (int c = 0; c < NCH; c++) {
        const size_t o = (size_t)c * (Bsz * Dsz) + lane;
        carry[o] = cv;
        cv = hend[o] + aprod[o] * cv;
    }
}

// ---------------- chunked scan: phase 3 (rescan + split output) ---------------
__global__ void scan3_k(const float* __restrict__ x, const float* __restrict__ g,
                        const float* __restrict__ carry,
                        __nv_bfloat16* __restrict__ hh, __nv_bfloat16* __restrict__ hl) {
    int bx = blockIdx.x;
    int c = bx >> 6;
    int rem = bx & 63;
    int b = rem >> 2;
    int d = ((rem & 3) << 7) + threadIdx.x;
    size_t base = (size_t)b * Lsz * Dsz + d;
    const float* gb = g + (size_t)b * Lsz;
    const int l0 = c * SCH;
    float hv = carry[(size_t)c * (Bsz * Dsz) + (size_t)b * Dsz + d];
    for (int l = l0; l < l0 + SCH; l += 8) {
        float xs[8], gs[8];
#pragma unroll
        for (int j = 0; j < 8; j++) {
            xs[j] = x[base + (size_t)(l + j) * Dsz];
            gs[j] = gb[l + j];
        }
#pragma unroll
        for (int j = 0; j < 8; j++) {
            hv = fmaf(gs[j], xs[j] - hv, hv);
            __nv_bfloat16 hi = __float2bfloat16(hv);
            size_t o = base + (size_t)(l + j) * Dsz;
            hh[o] = hi;
            hl[o] = __float2bfloat16(hv - __bfloat162float(hi));
        }
    }
}

// ---------------- launch --------------------------------------------------------
extern "C" void kernel_launch(void* const* d_in, const int* in_sizes, int n_in,
                              void* d_out, int out_size) {
    const int* x = (const int*)d_in[0];
    const float* ln_g = (const float*)d_in[1];
    const float* ln_b = (const float*)d_in[2];
    const float* conv_w = (const float*)d_in[3];
    const float* conv_b = (const float*)d_in[4];
    const float* wg = (const float*)d_in[5];
    const float* bg = (const float*)d_in[6];
    const float* wout = (const float*)d_in[7];
    const float* bout = (const float*)d_in[8];
    const float* fc_w = (const float*)d_in[9];
    const float* fc_b = (const float*)d_in[10];
    const float* mo_w = (const float*)d_in[11];
    const float* mo_b = (const float*)d_in[12];
    const float* lnf_g = (const float*)d_in[13];
    const float* lnf_b = (const float*)d_in[14];
    const float* head_w = (const float*)d_in[15];
    const float* head_b = (const float*)d_in[16];

    float *y, *z2, *gt, *hend, *aprod, *carry;
    __nv_bfloat16 *zh, *zl, *hh, *hl, *gh, *gl, *wh, *wl;
    cudaGetSymbolAddress((void**)&y, g_y);
    cudaGetSymbolAddress((void**)&z2, g_z2);
    cudaGetSymbolAddress((void**)&gt, g_gate);
    cudaGetSymbolAddress((void**)&hend, g_hend);
    cudaGetSymbolAddress((void**)&aprod, g_aprod);
    cudaGetSymbolAddress((void**)&carry, g_carry);
    cudaGetSymbolAddress((void**)&zh, g_zh);
    cudaGetSymbolAddress((void**)&zl, g_zl);
    cudaGetSymbolAddress((void**)&hh, g_hh);
    cudaGetSymbolAddress((void**)&hl, g_hl);
    cudaGetSymbolAddress((void**)&gh, g_gh);
    cudaGetSymbolAddress((void**)&gl, g_gl);
    cudaGetSymbolAddress((void**)&wh, g_wh);
    cudaGetSymbolAddress((void**)&wl, g_wl);

    cudaFuncSetAttribute(mma_gemm_k, cudaFuncAttributeMaxDynamicSharedMemorySize, GSMEM);
    cudaFuncSetAttribute(mma_fc_k, cudaFuncAttributeMaxDynamicSharedMemorySize, FCSMEM);

    const dim3 g512(4, Tsz / 128);

    // ---- one-time: embed residual + all weight splits ----
    embed_k<<<(Tsz * Dsz) / 256, 256>>>(x, y);
    cwsplit_k<<<(NLsz * 3 * DD) / 256, 256>>>(conv_w, wh + W_CONV(0), wl + W_CONV(0));
    wsplit_k<<<(NLsz * DD) / 256, 256>>>(wout, wh + W_WOUT(0), wl + W_WOUT(0), NLsz * DD);
    wsplit_k<<<(NLsz * 2 * DD) / 256, 256>>>(fc_w, wh + W_FC(0), wl + W_FC(0), NLsz * 2 * DD);
    wsplit_k<<<(NLsz * DD) / 256, 256>>>(mo_w, wh + W_MO(0), wl + W_MO(0), NLsz * DD);
    wsplit_k<<<DD / 256, 256>>>(head_w, wh + W_HEAD, wl + W_HEAD, DD);

    for (int i = 0; i < NLsz; i++) {
        if (i == 0)
            ln0_split_k<<<Tsz, 128>>>(x, zh, zl, ln_g, ln_b);
        else
            ln_split_k<<<Tsz, 128>>>(y, zh, zl, ln_g + (size_t)i * Dsz, ln_b + (size_t)i * Dsz);
        // conv: 3 shifted passes accumulated in registers
        mma_gemm_k<<<g512, 512, GSMEM>>>(zh, zl, wh + W_CONV(i), wl + W_CONV(i),
                                         conv_b + (size_t)i * Dsz, z2, nullptr, nullptr,
                                         Dsz, 3, -1, 0, 1, 1);
        gate_k<<<Tsz / 4, 128>>>(z2, wg + (size_t)i * Dsz, bg + i, gt);
        scan1_k<<<NCH * 64, 128>>>(z2, gt, hend, aprod);
        scan2_k<<<(Bsz * Dsz) / 128, 128>>>(hend, aprod, carry);
        scan3_k<<<NCH * 64, 128>>>(z2, gt, carry, hh, hl);
        // wout: split-bf16 output into zh/zl
        mma_gemm_k<<<g512, 512, GSMEM>>>(hh, hl, wh + W_WOUT(i), wl + W_WOUT(i),
                                         bout + (size_t)i * Dsz, nullptr, zh, zl,
                                         Dsz, 1, 0, 0, 0, 5);
        // fc + gated-MLP fused
        mma_fc_k<<<g512, 512, FCSMEM>>>(zh, zl, wh + W_FC(i), wl + W_FC(i),
                                        fc_b + (size_t)i * 2 * Dsz, gh, gl);
        // mo with residual accumulate into y
        mma_gemm_k<<<g512, 512, GSMEM>>>(gh, gl, wh + W_MO(i), wl + W_MO(i),
                                         mo_b + (size_t)i * Dsz, y, nullptr, nullptr,
                                         Dsz, 1, 0, 0, 0, 3);
    }

    ln_split_k<<<Tsz, 128>>>(y, zh, zl, lnf_g, lnf_b);
    mma_gemm_k<<<g512, 512, GSMEM>>>(zh, zl, wh + W_HEAD, wl + W_HEAD, head_b,
                                     (float*)d_out, nullptr, nullptr, Dsz, 1, 0, 0, 0, 1);
}